// round 11
// baseline (speedup 1.0000x reference)
#include <cuda_runtime.h>
#include <math.h>

// ---------------------------------------------------------------------------
// CoDAConv2d rewritten (single fused kernel):
//   act_o  = sum_c x_c * (A_o^T nb)_c + nb.b_o
//   norm_o = sqrt(x^T G_o x + 2 u_o^T x + s_o) + eps
// Thread t=(o,c,s): 16 o x 8 c x 2 s = 256 threads; s splits the 4 packed
// channel pairs (F table halved -> 2 CTAs/SM, 16 warps). Groups processed in
// pairs: conv(g), conv(g+1), then dual interleaved 4-stage butterfly so the
// shfl chains overlap the second conv body. Block-0 fused prep with spin;
// atomic task scheduler with prefetch; rsqrt epilogue.
// ---------------------------------------------------------------------------

#define B_  4
#define CI  8
#define CO  16
#define HH  112
#define WW  112
#define PATCH 72

#define CHUNK 16
#define COLS  (CHUNK + 2)               // 18
#define TILE_ELEMS (3 * COLS * 8)       // 432
#define NCHUNK (WW / CHUNK)             // 7
#define NTASK  (B_ * HH * NCHUNK)       // 3136
#define NT 256
#define GRID   296                      // 148 SMs * 2 blocks (all resident)

typedef unsigned long long ull;

// packed-pair tables (index t127 = o*8+c)
__device__ ull   gF2[36 * 128];   // [i*9+j][t127] : (F[c'=2i], F[c'=2i+1]) tap j
__device__ float gZ[9 * 128];
__device__ ull   gQ2[4 * 128];
__device__ float gU[128];
__device__ float gS[128];
__device__ int   gCtr  = 0;
__device__ int   gDone = 0;
__device__ int   gFlag = 0;

// --- f32x2 helpers -----------------------------------------------------------
__device__ __forceinline__ ull ffma2(ull a, ull b, ull c) {
    ull d; asm("fma.rn.f32x2 %0, %1, %2, %3;" : "=l"(d) : "l"(a), "l"(b), "l"(c));
    return d;
}
__device__ __forceinline__ ull fadd2(ull a, ull b) {
    ull d; asm("add.rn.f32x2 %0, %1, %2;" : "=l"(d) : "l"(a), "l"(b));
    return d;
}
__device__ __forceinline__ ull pack2(float lo, float hi) {
    ull d; asm("mov.b64 %0, {%1, %2};" : "=l"(d) : "f"(lo), "f"(hi));
    return d;
}
__device__ __forceinline__ float hsum2(ull a) {
    float lo, hi; asm("mov.b64 {%0, %1}, %2;" : "=f"(lo), "=f"(hi) : "l"(a));
    return lo + hi;
}

// --- prefetch loader (256 threads, 2 regs each) -------------------------------
__device__ __forceinline__ void load_task(const float* __restrict__ in,
                                          int task, int t, float pre[2]) {
    const int rowid = task / NCHUNK;
    const int cw    = (task % NCHUNK) * CHUNK;
    const int b     = rowid / HH;
    const int h     = rowid % HH;
    #pragma unroll
    for (int k = 0; k < 2; k++) {
        int idx = t + k * NT;
        float v = 0.f;
        if (idx < TILE_ELEMS) {
            int ch   = idx & 7;
            int rest = idx >> 3;
            int col  = rest % COLS;
            int r    = rest / COLS;
            int ir   = h - 1 + r;
            int ic   = cw - 1 + col;
            if ((unsigned)ir < (unsigned)HH && (unsigned)ic < (unsigned)WW)
                v = __ldg(&in[((b * CI + ch) * HH + ir) * WW + ic]);
        }
        pre[k] = v;
    }
}

// --- one group's conv (s-split): r[0..3]=av partial, r[4..7]=qv partial ------
__device__ __forceinline__ void conv_group(const float tile[3][COLS][8],
                                           int wlb, int c, int s,
                                           const ull* Fp, const float* Zreg,
                                           const ull* Qp, ull qinit, float Qs,
                                           float r[8]) {
    ull  m0[4], m1[4];
    float z[4], xc[4];
    ull  qp[4];
    #pragma unroll
    for (int px = 0; px < 4; px++) { m0[px] = 0ull; m1[px] = 0ull; z[px] = 0.f; }

    #pragma unroll
    for (int dh = 0; dh < 3; dh++) {
        #pragma unroll
        for (int k = 0; k < 6; k++) {
            const float* pv = &tile[dh][wlb + k][0];
            const ulonglong2 V = ((const ulonglong2*)pv)[s];   // this half's 2 pairs
            const float vc = pv[c];

            const int pxlo = (k - 2 > 0) ? (k - 2) : 0;
            const int pxhi = (k < 3) ? k : 3;
            #pragma unroll
            for (int px = pxlo; px <= pxhi; px++) {
                const int j = dh * 3 + (k - px);
                m0[px] = ffma2(V.x, Fp[0 + j], m0[px]);
                m1[px] = ffma2(V.y, Fp[9 + j], m1[px]);
                z[px]  = fmaf(vc, Zreg[j], z[px]);   // Zreg=0 on s=1 lanes
            }
            if (dh == 1 && k >= 1 && k <= 4) {
                const int px = k - 1;
                xc[px] = vc;
                qp[px] = fadd2(ffma2(V.x, Qp[0], qinit),
                               ffma2(V.y, Qp[1], 0ull));
            }
        }
    }

    #pragma unroll
    for (int px = 0; px < 4; px++) {
        float m = hsum2(fadd2(m0[px], m1[px]));
        r[px]     = fmaf(xc[px], m, z[px]);
        r[px + 4] = fmaf(xc[px], hsum2(qp[px]), Qs);
    }
}

// --- main kernel ----------------------------------------------------------------
__global__ __launch_bounds__(NT, 2)
void coda_main_kernel(const float* __restrict__ in,
                      const float* __restrict__ w_pred,
                      const float* __restrict__ b_pred,
                      float* __restrict__ out) {
    const int t    = threadIdx.x;
    const int c    = t & 7;
    const int s    = (t >> 3) & 1;
    const int o    = t >> 4;
    const int t127 = o * 8 + c;

    // ===== fused prep: block 0 (first 128 threads) builds tables ============
    if (blockIdx.x == 0) {
        if (t < 128) {
            const int po = t >> 3, pc = t & 7;
            #pragma unroll 4
            for (int bx = 0; bx < 36; bx++) {
                const int i = bx / 9, j = bx % 9;
                float lo = w_pred[(((2 * i)     * 9 + j) * 16 + po) * 8 + pc];
                float hi = w_pred[(((2 * i + 1) * 9 + j) * 16 + po) * 8 + pc];
                gF2[bx * 128 + t] = pack2(lo, hi);
                if (bx < 9) gZ[bx * 128 + t] = b_pred[(pc * 9 + bx) * 16 + po];
            }
            float G8[8] = {0.f, 0.f, 0.f, 0.f, 0.f, 0.f, 0.f, 0.f};
            float uacc = 0.f, ssum = 0.f;
            #pragma unroll 4
            for (int p = 0; p < PATCH; p++) {
                const float wc = w_pred[(p * 16 + po) * 8 + pc];
                const float4 k0 = *(const float4*)&w_pred[(p * 16 + po) * 8];
                const float4 k1 = *(const float4*)&w_pred[(p * 16 + po) * 8 + 4];
                const float bv = b_pred[p * 16 + po];
                G8[0] = fmaf(wc, k0.x, G8[0]); G8[1] = fmaf(wc, k0.y, G8[1]);
                G8[2] = fmaf(wc, k0.z, G8[2]); G8[3] = fmaf(wc, k0.w, G8[3]);
                G8[4] = fmaf(wc, k1.x, G8[4]); G8[5] = fmaf(wc, k1.y, G8[5]);
                G8[6] = fmaf(wc, k1.z, G8[6]); G8[7] = fmaf(wc, k1.w, G8[7]);
                uacc = fmaf(wc, bv, uacc);
                ssum = fmaf(bv, bv, ssum);
            }
            #pragma unroll
            for (int kk = 0; kk < 4; kk++)
                gQ2[kk * 128 + t] = pack2(G8[2 * kk], G8[2 * kk + 1]);
            gU[t] = 2.0f * uacc;
            gS[t] = ssum * 0.125f;
            __threadfence();
        }
        __syncthreads();
        if (t == 0) atomicExch(&gFlag, 1);   // release
    }

    // ===== grab first task + prefetch (overlaps block-0 prep) ===============
    __shared__ float tile[3][COLS][8];
    __shared__ int   sTask;

    if (t == 0) sTask = atomicAdd(&gCtr, 1);
    __syncthreads();
    int task = sTask;

    float pre[2];
    if (task < NTASK) load_task(in, task, t, pre);

    if (blockIdx.x != 0) {
        if (t == 0) {
            while (atomicAdd(&gFlag, 0) == 0) __nanosleep(64);
        }
        __syncthreads();
        __threadfence();                      // acquire
    }

    // ===== per-thread constant tables (this s-half only) ====================
    ull Fp[18];
    #pragma unroll
    for (int e = 0; e < 2; e++)
        #pragma unroll
        for (int j = 0; j < 9; j++)
            Fp[e * 9 + j] = gF2[((2 * s + e) * 9 + j) * 128 + t127];

    float Zreg[9];
    #pragma unroll
    for (int j = 0; j < 9; j++) Zreg[j] = s ? 0.f : gZ[j * 128 + t127];

    ull Qp[2];
    #pragma unroll
    for (int e = 0; e < 2; e++) Qp[e] = gQ2[(2 * s + e) * 128 + t127];
    const ull   qinit = s ? 0ull : pack2(gU[t127], 0.f);
    const float Qs    = gS[t127] * 0.5f;     // s[o]/16, summed over 16 lanes

    if (task < NTASK) {
        while (true) {
            #pragma unroll
            for (int k = 0; k < 2; k++) {
                int idx = t + k * NT;
                if (idx < TILE_ELEMS) ((float*)tile)[idx] = pre[k];
            }
            if (t == 0) sTask = atomicAdd(&gCtr, 1);
            __syncthreads();
            const int nxt = sTask;
            if (nxt < NTASK) load_task(in, nxt, t, pre);

            const int rowid = task / NCHUNK;
            const int cw    = (task % NCHUNK) * CHUNK;
            const int b     = rowid / HH;
            const int h     = rowid % HH;
            float* orow = &out[((b * CO + o) * HH + h) * WW + cw];

            // paired groups: conv A, conv B, dual interleaved reduction
            #pragma unroll 1
            for (int half = 0; half < 2; half++) {
                const int wlbA = half * 8;
                const int wlbB = wlbA + 4;

                float rA[8], rB[8];
                conv_group(tile, wlbA, c, s, Fp, Zreg, Qp, qinit, Qs, rA);
                conv_group(tile, wlbB, c, s, Fp, Zreg, Qp, qinit, Qs, rB);

                // dual interleaved butterfly: bits 0..2 (c), then bit 3 (s)
                const bool h0 = c & 1, h1 = c & 2, h2 = c & 4;
                float sA[4], sB[4];
                #pragma unroll
                for (int i = 0; i < 4; i++) {
                    float gA = h0 ? rA[2 * i] : rA[2 * i + 1];
                    float gB = h0 ? rB[2 * i] : rB[2 * i + 1];
                    float dA = __shfl_xor_sync(0xffffffffu, gA, 1);
                    float dB = __shfl_xor_sync(0xffffffffu, gB, 1);
                    sA[i] = (h0 ? rA[2 * i + 1] : rA[2 * i]) + dA;
                    sB[i] = (h0 ? rB[2 * i + 1] : rB[2 * i]) + dB;
                }
                float uA[2], uB[2];
                #pragma unroll
                for (int i = 0; i < 2; i++) {
                    float gA = h1 ? sA[2 * i] : sA[2 * i + 1];
                    float gB = h1 ? sB[2 * i] : sB[2 * i + 1];
                    float dA = __shfl_xor_sync(0xffffffffu, gA, 2);
                    float dB = __shfl_xor_sync(0xffffffffu, gB, 2);
                    uA[i] = (h1 ? sA[2 * i + 1] : sA[2 * i]) + dA;
                    uB[i] = (h1 ? sB[2 * i + 1] : sB[2 * i]) + dB;
                }
                {
                    float gA = h2 ? uA[0] : uA[1];
                    float gB = h2 ? uB[0] : uB[1];
                    float dA = __shfl_xor_sync(0xffffffffu, gA, 4);
                    float dB = __shfl_xor_sync(0xffffffffu, gB, 4);
                    float totA = (h2 ? uA[1] : uA[0]) + dA;
                    float totB = (h2 ? uB[1] : uB[0]) + dB;
                    totA += __shfl_xor_sync(0xffffffffu, totA, 8);  // fold s
                    totB += __shfl_xor_sync(0xffffffffu, totB, 8);
                    float othA = __shfl_xor_sync(0xffffffffu, totA, 4);
                    float othB = __shfl_xor_sync(0xffffffffu, totB, 4);
                    if (c < 4 && s == 0) {
                        // reference denom = sqrt(qv)+1e-6; qv bounded away
                        // from 0, so av*rsqrt(qv) is within ~1e-5 rel of it.
                        float qA = fmaxf(othA, 1e-20f);
                        float qB = fmaxf(othB, 1e-20f);
                        orow[wlbA + c] = totA * rsqrtf(qA);
                        orow[wlbB + c] = totB * rsqrtf(qB);
                    }
                }
            }

            __syncthreads();
            if (nxt >= NTASK) break;
            task = nxt;
        }
    }

    // ---- reset for next graph replay: last block out resets everything ----
    if (t == 0) {
        int old = atomicAdd(&gDone, 1);
        if (old == (int)gridDim.x - 1) {
            atomicExch(&gCtr, 0);
            atomicExch(&gFlag, 0);
            atomicExch(&gDone, 0);
        }
    }
}

// ---------------------------------------------------------------------------
extern "C" void kernel_launch(void* const* d_in, const int* in_sizes, int n_in,
                              void* d_out, int out_size) {
    const float* in_tensor = (const float*)d_in[0];
    const float* w_pred    = (const float*)d_in[1];
    const float* b_pred    = (const float*)d_in[2];
    float* out = (float*)d_out;

    coda_main_kernel<<<GRID, NT>>>(in_tensor, w_pred, b_pred, out);
}

// round 12
// speedup vs baseline: 1.1023x; 1.1023x over previous
#include <cuda_runtime.h>
#include <math.h>

// ---------------------------------------------------------------------------
// CoDAConv2d rewritten (single fused kernel, paired-group reduction hiding,
// fine-grained 8-pixel tasks for low straggler tail):
//   act_o  = sum_c x_c * (A_o^T nb)_c + nb.b_o
//   norm_o = sqrt(x^T G_o x + 2 u_o^T x + s_o) + eps
// Thread t=(o,c). f32x2 packed FMA; 4px register blocking; each task is one
// group PAIR: conv(g0), conv(g1), dual interleaved butterfly (shfl chains
// overlap the second conv body). rsqrt epilogue; block-0 fused prep with
// spin; atomic task scheduler with prefetch. 6272 tasks / 444 blocks keeps
// the dynamic-scheduling makespan tail at ~6% (was ~13% with 16px tasks).
// ---------------------------------------------------------------------------

#define B_  4
#define CI  8
#define CO  16
#define HH  112
#define WW  112
#define PATCH 72

#define CHUNK 8
#define COLS  (CHUNK + 2)               // 10
#define TILE_ELEMS (3 * COLS * 8)       // 240
#define NCHUNK (WW / CHUNK)             // 14
#define NTASK  (B_ * HH * NCHUNK)       // 6272
#define GRID   444                      // 148 SMs * 3 blocks (all resident)

typedef unsigned long long ull;

// packed-pair tables (index t = o*8+c)
__device__ ull   gF2[36 * 128];
__device__ float gZ[9 * 128];
__device__ ull   gQ2[4 * 128];
__device__ float gU[128];
__device__ float gS[128];
__device__ int   gCtr  = 0;
__device__ int   gDone = 0;
__device__ int   gFlag = 0;

// --- f32x2 helpers -----------------------------------------------------------
__device__ __forceinline__ ull ffma2(ull a, ull b, ull c) {
    ull d; asm("fma.rn.f32x2 %0, %1, %2, %3;" : "=l"(d) : "l"(a), "l"(b), "l"(c));
    return d;
}
__device__ __forceinline__ ull fadd2(ull a, ull b) {
    ull d; asm("add.rn.f32x2 %0, %1, %2;" : "=l"(d) : "l"(a), "l"(b));
    return d;
}
__device__ __forceinline__ ull pack2(float lo, float hi) {
    ull d; asm("mov.b64 %0, {%1, %2};" : "=l"(d) : "f"(lo), "f"(hi));
    return d;
}
__device__ __forceinline__ float hsum2(ull a) {
    float lo, hi; asm("mov.b64 {%0, %1}, %2;" : "=f"(lo), "=f"(hi) : "l"(a));
    return lo + hi;
}

// --- prefetch loader (240 elems, 2 regs per thread) ---------------------------
__device__ __forceinline__ void load_task(const float* __restrict__ in,
                                          int task, int t, float pre[2]) {
    const int rowid = task / NCHUNK;
    const int cw    = (task % NCHUNK) * CHUNK;
    const int b     = rowid / HH;
    const int h     = rowid % HH;
    #pragma unroll
    for (int k = 0; k < 2; k++) {
        int idx = t + k * 128;
        float v = 0.f;
        if (idx < TILE_ELEMS) {
            int ch   = idx & 7;
            int rest = idx >> 3;
            int col  = rest % COLS;
            int r    = rest / COLS;
            int ir   = h - 1 + r;
            int ic   = cw - 1 + col;
            if ((unsigned)ir < (unsigned)HH && (unsigned)ic < (unsigned)WW)
                v = __ldg(&in[((b * CI + ch) * HH + ir) * WW + ic]);
        }
        pre[k] = v;
    }
}

// --- one group's conv: produces r[0..3]=av partials, r[4..7]=qv partials -----
__device__ __forceinline__ void conv_group(const float tile[3][COLS][8],
                                           int wlb, int c,
                                           const ull* Fp, const float* Zreg,
                                           const ull* Qp, ull qinit, float Qs,
                                           float r[8]) {
    ull  m0[4], m1[4], m2[4], m3[4];
    float z[4], xc[4];
    ull  qp[4];
    #pragma unroll
    for (int px = 0; px < 4; px++) {
        m0[px] = 0ull; m1[px] = 0ull; m2[px] = 0ull; m3[px] = 0ull;
        z[px] = 0.f;
    }

    #pragma unroll
    for (int dh = 0; dh < 3; dh++) {
        #pragma unroll
        for (int k = 0; k < 6; k++) {
            const float* pv = &tile[dh][wlb + k][0];
            const ulonglong2 VA = *(const ulonglong2*)pv;
            const ulonglong2 VB = *((const ulonglong2*)pv + 1);
            const float vc = pv[c];

            const int pxlo = (k - 2 > 0) ? (k - 2) : 0;
            const int pxhi = (k < 3) ? k : 3;
            #pragma unroll
            for (int px = pxlo; px <= pxhi; px++) {
                const int j = dh * 3 + (k - px);
                m0[px] = ffma2(VA.x, Fp[ 0 + j], m0[px]);
                m1[px] = ffma2(VA.y, Fp[ 9 + j], m1[px]);
                m2[px] = ffma2(VB.x, Fp[18 + j], m2[px]);
                m3[px] = ffma2(VB.y, Fp[27 + j], m3[px]);
                z[px]  = fmaf(vc, Zreg[j], z[px]);
            }
            if (dh == 1 && k >= 1 && k <= 4) {
                const int px = k - 1;
                xc[px] = vc;
                ull qa = ffma2(VA.x, Qp[0], qinit);
                qa = ffma2(VB.x, Qp[2], qa);
                ull qb = ffma2(VA.y, Qp[1], 0ull);
                qb = ffma2(VB.y, Qp[3], qb);
                qp[px] = fadd2(qa, qb);
            }
        }
    }

    #pragma unroll
    for (int px = 0; px < 4; px++) {
        float m = hsum2(fadd2(fadd2(m0[px], m1[px]), fadd2(m2[px], m3[px])));
        r[px]     = fmaf(xc[px], m, z[px]);
        r[px + 4] = fmaf(xc[px], hsum2(qp[px]), Qs);
    }
}

// --- main kernel ----------------------------------------------------------------
__global__ __launch_bounds__(128, 3)
void coda_main_kernel(const float* __restrict__ in,
                      const float* __restrict__ w_pred,
                      const float* __restrict__ b_pred,
                      float* __restrict__ out) {
    const int t = threadIdx.x;
    const int o = t >> 3;
    const int c = t & 7;

    // ===== fused prep: block 0 builds tables; everyone else waits ==========
    if (blockIdx.x == 0) {
        #pragma unroll 4
        for (int bx = 0; bx < 36; bx++) {
            const int i = bx / 9, j = bx % 9;
            float lo = w_pred[(((2 * i)     * 9 + j) * 16 + o) * 8 + c];
            float hi = w_pred[(((2 * i + 1) * 9 + j) * 16 + o) * 8 + c];
            gF2[bx * 128 + t] = pack2(lo, hi);
            if (bx < 9) gZ[bx * 128 + t] = b_pred[(c * 9 + bx) * 16 + o];
        }
        float G8[8] = {0.f, 0.f, 0.f, 0.f, 0.f, 0.f, 0.f, 0.f};
        float uacc = 0.f, ssum = 0.f;
        #pragma unroll 4
        for (int p = 0; p < PATCH; p++) {
            const float wc = w_pred[(p * 16 + o) * 8 + c];
            const float4 k0 = *(const float4*)&w_pred[(p * 16 + o) * 8];
            const float4 k1 = *(const float4*)&w_pred[(p * 16 + o) * 8 + 4];
            const float bv = b_pred[p * 16 + o];
            G8[0] = fmaf(wc, k0.x, G8[0]); G8[1] = fmaf(wc, k0.y, G8[1]);
            G8[2] = fmaf(wc, k0.z, G8[2]); G8[3] = fmaf(wc, k0.w, G8[3]);
            G8[4] = fmaf(wc, k1.x, G8[4]); G8[5] = fmaf(wc, k1.y, G8[5]);
            G8[6] = fmaf(wc, k1.z, G8[6]); G8[7] = fmaf(wc, k1.w, G8[7]);
            uacc = fmaf(wc, bv, uacc);
            ssum = fmaf(bv, bv, ssum);
        }
        #pragma unroll
        for (int kk = 0; kk < 4; kk++)
            gQ2[kk * 128 + t] = pack2(G8[2 * kk], G8[2 * kk + 1]);
        gU[t] = 2.0f * uacc;
        gS[t] = ssum * 0.125f;

        __threadfence();
        __syncthreads();
        if (t == 0) atomicExch(&gFlag, 1);   // release
    } else {
        if (t == 0) {
            while (atomicAdd(&gFlag, 0) == 0) __nanosleep(64);
        }
        __syncthreads();
        __threadfence();                      // acquire
    }

    // ===== per-thread constant tables =======================================
    ull Fp[36];
    #pragma unroll
    for (int p = 0; p < 36; p++) Fp[p] = gF2[p * 128 + t];
    float Zreg[9];
    #pragma unroll
    for (int j = 0; j < 9; j++) Zreg[j] = gZ[j * 128 + t];
    ull Qp[4];
    #pragma unroll
    for (int k = 0; k < 4; k++) Qp[k] = gQ2[k * 128 + t];
    const ull   qinit = pack2(gU[t], 0.f);
    const float Qs    = gS[t];

    __shared__ float tile[3][COLS][8];
    __shared__ int   sTask;

    float pre[2];

    if (t == 0) sTask = atomicAdd(&gCtr, 1);
    __syncthreads();
    int task = sTask;
    if (task < NTASK) {
        load_task(in, task, t, pre);

        while (true) {
            #pragma unroll
            for (int k = 0; k < 2; k++) {
                int idx = t + k * 128;
                if (idx < TILE_ELEMS) ((float*)tile)[idx] = pre[k];
            }
            if (t == 0) sTask = atomicAdd(&gCtr, 1);
            __syncthreads();
            const int nxt = sTask;
            if (nxt < NTASK) load_task(in, nxt, t, pre);

            const int rowid = task / NCHUNK;
            const int cw    = (task % NCHUNK) * CHUNK;
            const int b     = rowid / HH;
            const int h     = rowid % HH;
            float* orow = &out[((b * CO + o) * HH + h) * WW + cw];

            // the task IS one group pair: conv A, conv B, dual reduction
            {
                const int wlbA = 0;
                const int wlbB = 4;

                float rA[8], rB[8];
                conv_group(tile, wlbA, c, Fp, Zreg, Qp, qinit, Qs, rA);
                conv_group(tile, wlbB, c, Fp, Zreg, Qp, qinit, Qs, rB);

                // dual interleaved 8-value / 8-lane butterfly reductions
                const bool h0 = c & 1, h1 = c & 2, h2 = c & 4;
                float sA[4], sB[4];
                #pragma unroll
                for (int i = 0; i < 4; i++) {
                    float gA = h0 ? rA[2 * i] : rA[2 * i + 1];
                    float gB = h0 ? rB[2 * i] : rB[2 * i + 1];
                    float dA = __shfl_xor_sync(0xffffffffu, gA, 1);
                    float dB = __shfl_xor_sync(0xffffffffu, gB, 1);
                    sA[i] = (h0 ? rA[2 * i + 1] : rA[2 * i]) + dA;
                    sB[i] = (h0 ? rB[2 * i + 1] : rB[2 * i]) + dB;
                }
                float uA[2], uB[2];
                #pragma unroll
                for (int i = 0; i < 2; i++) {
                    float gA = h1 ? sA[2 * i] : sA[2 * i + 1];
                    float gB = h1 ? sB[2 * i] : sB[2 * i + 1];
                    float dA = __shfl_xor_sync(0xffffffffu, gA, 2);
                    float dB = __shfl_xor_sync(0xffffffffu, gB, 2);
                    uA[i] = (h1 ? sA[2 * i + 1] : sA[2 * i]) + dA;
                    uB[i] = (h1 ? sB[2 * i + 1] : sB[2 * i]) + dB;
                }
                {
                    float gA = h2 ? uA[0] : uA[1];
                    float gB = h2 ? uB[0] : uB[1];
                    float dA = __shfl_xor_sync(0xffffffffu, gA, 4);
                    float dB = __shfl_xor_sync(0xffffffffu, gB, 4);
                    float totA = (h2 ? uA[1] : uA[0]) + dA;
                    float totB = (h2 ? uB[1] : uB[0]) + dB;
                    float othA = __shfl_xor_sync(0xffffffffu, totA, 4);
                    float othB = __shfl_xor_sync(0xffffffffu, totB, 4);
                    if (c < 4) {
                        // reference denom = sqrt(qv)+1e-6; qv bounded away
                        // from 0, so av*rsqrt(qv) is within ~1e-5 rel of it.
                        float qA = fmaxf(othA, 1e-20f);
                        float qB = fmaxf(othB, 1e-20f);
                        orow[wlbA + c] = totA * rsqrtf(qA);
                        orow[wlbB + c] = totB * rsqrtf(qB);
                    }
                }
            }

            __syncthreads();
            if (nxt >= NTASK) break;
            task = nxt;
        }
    }

    // ---- reset for next graph replay: last block out resets everything ----
    if (t == 0) {
        int old = atomicAdd(&gDone, 1);
        if (old == (int)gridDim.x - 1) {
            atomicExch(&gCtr, 0);
            atomicExch(&gFlag, 0);
            atomicExch(&gDone, 0);
        }
    }
}

// ---------------------------------------------------------------------------
extern "C" void kernel_launch(void* const* d_in, const int* in_sizes, int n_in,
                              void* d_out, int out_size) {
    const float* in_tensor = (const float*)d_in[0];
    const float* w_pred    = (const float*)d_in[1];
    const float* b_pred    = (const float*)d_in[2];
    float* out = (float*)d_out;

    coda_main_kernel<<<GRID, 128>>>(in_tensor, w_pred, b_pred, out);
}

// round 13
// speedup vs baseline: 1.1874x; 1.0771x over previous
#include <cuda_runtime.h>
#include <math.h>

// ---------------------------------------------------------------------------
// CoDAConv2d rewritten (single fused kernel, paired-group reduction hiding,
// double-buffered tile -> ONE __syncthreads per task):
//   act_o  = sum_c x_c * (A_o^T nb)_c + nb.b_o
//   norm_o = sqrt(x^T G_o x + 2 u_o^T x + s_o) + eps
// Thread t=(o,c). f32x2 packed FMA; 4px register blocking; groups processed
// in pairs with dual interleaved butterfly; rsqrt epilogue; block-0 fused
// prep with spin; atomic task scheduler with prefetch.
// Safety of single sync: a warp reaches sync(i) only after compute(i-1), so
// when any warp publishes into buffer (i+1)&1 == (i-1)&1, all warps have
// finished reading it.
// ---------------------------------------------------------------------------

#define B_  4
#define CI  8
#define CO  16
#define HH  112
#define WW  112
#define PATCH 72

#define CHUNK 16
#define COLS  (CHUNK + 2)               // 18
#define TILE_ELEMS (3 * COLS * 8)       // 432
#define NCHUNK (WW / CHUNK)             // 7
#define NTASK  (B_ * HH * NCHUNK)       // 3136
#define GRID   444                      // 148 SMs * 3 blocks (all resident)

typedef unsigned long long ull;

// packed-pair tables (index t = o*8+c)
__device__ ull   gF2[36 * 128];
__device__ float gZ[9 * 128];
__device__ ull   gQ2[4 * 128];
__device__ float gU[128];
__device__ float gS[128];
__device__ int   gCtr  = 0;
__device__ int   gDone = 0;
__device__ int   gFlag = 0;

// --- f32x2 helpers -----------------------------------------------------------
__device__ __forceinline__ ull ffma2(ull a, ull b, ull c) {
    ull d; asm("fma.rn.f32x2 %0, %1, %2, %3;" : "=l"(d) : "l"(a), "l"(b), "l"(c));
    return d;
}
__device__ __forceinline__ ull fadd2(ull a, ull b) {
    ull d; asm("add.rn.f32x2 %0, %1, %2;" : "=l"(d) : "l"(a), "l"(b));
    return d;
}
__device__ __forceinline__ ull pack2(float lo, float hi) {
    ull d; asm("mov.b64 %0, {%1, %2};" : "=l"(d) : "f"(lo), "f"(hi));
    return d;
}
__device__ __forceinline__ float hsum2(ull a) {
    float lo, hi; asm("mov.b64 {%0, %1}, %2;" : "=f"(lo), "=f"(hi) : "l"(a));
    return lo + hi;
}

// --- prefetch loader --------------------------------------------------------
__device__ __forceinline__ void load_task(const float* __restrict__ in,
                                          int task, int t, float pre[4]) {
    const int rowid = task / NCHUNK;
    const int cw    = (task % NCHUNK) * CHUNK;
    const int b     = rowid / HH;
    const int h     = rowid % HH;
    #pragma unroll
    for (int k = 0; k < 4; k++) {
        int idx = t + k * 128;
        float v = 0.f;
        if (idx < TILE_ELEMS) {
            int ch   = idx & 7;
            int rest = idx >> 3;
            int col  = rest % COLS;
            int r    = rest / COLS;
            int ir   = h - 1 + r;
            int ic   = cw - 1 + col;
            if ((unsigned)ir < (unsigned)HH && (unsigned)ic < (unsigned)WW)
                v = __ldg(&in[((b * CI + ch) * HH + ir) * WW + ic]);
        }
        pre[k] = v;
    }
}

// --- one group's conv: produces r[0..3]=av partials, r[4..7]=qv partials -----
__device__ __forceinline__ void conv_group(const float tile[3][COLS][8],
                                           int wlb, int c,
                                           const ull* Fp, const float* Zreg,
                                           const ull* Qp, ull qinit, float Qs,
                                           float r[8]) {
    ull  m0[4], m1[4], m2[4], m3[4];
    float z[4], xc[4];
    ull  qp[4];
    #pragma unroll
    for (int px = 0; px < 4; px++) {
        m0[px] = 0ull; m1[px] = 0ull; m2[px] = 0ull; m3[px] = 0ull;
        z[px] = 0.f;
    }

    #pragma unroll
    for (int dh = 0; dh < 3; dh++) {
        #pragma unroll
        for (int k = 0; k < 6; k++) {
            const float* pv = &tile[dh][wlb + k][0];
            const ulonglong2 VA = *(const ulonglong2*)pv;
            const ulonglong2 VB = *((const ulonglong2*)pv + 1);
            const float vc = pv[c];

            const int pxlo = (k - 2 > 0) ? (k - 2) : 0;
            const int pxhi = (k < 3) ? k : 3;
            #pragma unroll
            for (int px = pxlo; px <= pxhi; px++) {
                const int j = dh * 3 + (k - px);
                m0[px] = ffma2(VA.x, Fp[ 0 + j], m0[px]);
                m1[px] = ffma2(VA.y, Fp[ 9 + j], m1[px]);
                m2[px] = ffma2(VB.x, Fp[18 + j], m2[px]);
                m3[px] = ffma2(VB.y, Fp[27 + j], m3[px]);
                z[px]  = fmaf(vc, Zreg[j], z[px]);
            }
            if (dh == 1 && k >= 1 && k <= 4) {
                const int px = k - 1;
                xc[px] = vc;
                ull qa = ffma2(VA.x, Qp[0], qinit);
                qa = ffma2(VB.x, Qp[2], qa);
                ull qb = ffma2(VA.y, Qp[1], 0ull);
                qb = ffma2(VB.y, Qp[3], qb);
                qp[px] = fadd2(qa, qb);
            }
        }
    }

    #pragma unroll
    for (int px = 0; px < 4; px++) {
        float m = hsum2(fadd2(fadd2(m0[px], m1[px]), fadd2(m2[px], m3[px])));
        r[px]     = fmaf(xc[px], m, z[px]);
        r[px + 4] = fmaf(xc[px], hsum2(qp[px]), Qs);
    }
}

// --- main kernel ----------------------------------------------------------------
__global__ __launch_bounds__(128, 3)
void coda_main_kernel(const float* __restrict__ in,
                      const float* __restrict__ w_pred,
                      const float* __restrict__ b_pred,
                      float* __restrict__ out) {
    const int t = threadIdx.x;
    const int o = t >> 3;
    const int c = t & 7;

    // ===== fused prep: block 0 builds tables; everyone else waits ==========
    if (blockIdx.x == 0) {
        #pragma unroll 4
        for (int bx = 0; bx < 36; bx++) {
            const int i = bx / 9, j = bx % 9;
            float lo = w_pred[(((2 * i)     * 9 + j) * 16 + o) * 8 + c];
            float hi = w_pred[(((2 * i + 1) * 9 + j) * 16 + o) * 8 + c];
            gF2[bx * 128 + t] = pack2(lo, hi);
            if (bx < 9) gZ[bx * 128 + t] = b_pred[(c * 9 + bx) * 16 + o];
        }
        float G8[8] = {0.f, 0.f, 0.f, 0.f, 0.f, 0.f, 0.f, 0.f};
        float uacc = 0.f, ssum = 0.f;
        #pragma unroll 4
        for (int p = 0; p < PATCH; p++) {
            const float wc = w_pred[(p * 16 + o) * 8 + c];
            const float4 k0 = *(const float4*)&w_pred[(p * 16 + o) * 8];
            const float4 k1 = *(const float4*)&w_pred[(p * 16 + o) * 8 + 4];
            const float bv = b_pred[p * 16 + o];
            G8[0] = fmaf(wc, k0.x, G8[0]); G8[1] = fmaf(wc, k0.y, G8[1]);
            G8[2] = fmaf(wc, k0.z, G8[2]); G8[3] = fmaf(wc, k0.w, G8[3]);
            G8[4] = fmaf(wc, k1.x, G8[4]); G8[5] = fmaf(wc, k1.y, G8[5]);
            G8[6] = fmaf(wc, k1.z, G8[6]); G8[7] = fmaf(wc, k1.w, G8[7]);
            uacc = fmaf(wc, bv, uacc);
            ssum = fmaf(bv, bv, ssum);
        }
        #pragma unroll
        for (int kk = 0; kk < 4; kk++)
            gQ2[kk * 128 + t] = pack2(G8[2 * kk], G8[2 * kk + 1]);
        gU[t] = 2.0f * uacc;
        gS[t] = ssum * 0.125f;

        __threadfence();
        __syncthreads();
        if (t == 0) atomicExch(&gFlag, 1);   // release
    } else {
        if (t == 0) {
            while (atomicAdd(&gFlag, 0) == 0) __nanosleep(64);
        }
        __syncthreads();
        __threadfence();                      // acquire
    }

    // ===== per-thread constant tables =======================================
    ull Fp[36];
    #pragma unroll
    for (int p = 0; p < 36; p++) Fp[p] = gF2[p * 128 + t];
    float Zreg[9];
    #pragma unroll
    for (int j = 0; j < 9; j++) Zreg[j] = gZ[j * 128 + t];
    ull Qp[4];
    #pragma unroll
    for (int k = 0; k < 4; k++) Qp[k] = gQ2[k * 128 + t];
    const ull   qinit = pack2(gU[t], 0.f);
    const float Qs    = gS[t];

    __shared__ float tile[2][3][COLS][8];   // double buffer
    __shared__ int   sTask;

    float pre[4];
    int buf = 0;

    if (t == 0) sTask = atomicAdd(&gCtr, 1);
    __syncthreads();
    int task = sTask;
    if (task < NTASK) {
        load_task(in, task, t, pre);

        while (true) {
            // publish prefetched tile into current buffer
            #pragma unroll
            for (int k = 0; k < 4; k++) {
                int idx = t + k * 128;
                if (idx < TILE_ELEMS) ((float*)tile[buf])[idx] = pre[k];
            }
            if (t == 0) sTask = atomicAdd(&gCtr, 1);
            __syncthreads();                   // single barrier per task
            const int nxt = sTask;
            if (nxt < NTASK) load_task(in, nxt, t, pre);

            const int rowid = task / NCHUNK;
            const int cw    = (task % NCHUNK) * CHUNK;
            const int b     = rowid / HH;
            const int h     = rowid % HH;
            float* orow = &out[((b * CO + o) * HH + h) * WW + cw];

            // paired groups: conv A, conv B, dual interleaved reduction
            #pragma unroll 1
            for (int half = 0; half < 2; half++) {
                const int wlbA = half * 8;
                const int wlbB = wlbA + 4;

                float rA[8], rB[8];
                conv_group(tile[buf], wlbA, c, Fp, Zreg, Qp, qinit, Qs, rA);
                conv_group(tile[buf], wlbB, c, Fp, Zreg, Qp, qinit, Qs, rB);

                // dual interleaved 8-value / 8-lane butterfly reductions
                const bool h0 = c & 1, h1 = c & 2, h2 = c & 4;
                float sA[4], sB[4];
                #pragma unroll
                for (int i = 0; i < 4; i++) {
                    float gA = h0 ? rA[2 * i] : rA[2 * i + 1];
                    float gB = h0 ? rB[2 * i] : rB[2 * i + 1];
                    float dA = __shfl_xor_sync(0xffffffffu, gA, 1);
                    float dB = __shfl_xor_sync(0xffffffffu, gB, 1);
                    sA[i] = (h0 ? rA[2 * i + 1] : rA[2 * i]) + dA;
                    sB[i] = (h0 ? rB[2 * i + 1] : rB[2 * i]) + dB;
                }
                float uA[2], uB[2];
                #pragma unroll
                for (int i = 0; i < 2; i++) {
                    float gA = h1 ? sA[2 * i] : sA[2 * i + 1];
                    float gB = h1 ? sB[2 * i] : sB[2 * i + 1];
                    float dA = __shfl_xor_sync(0xffffffffu, gA, 2);
                    float dB = __shfl_xor_sync(0xffffffffu, gB, 2);
                    uA[i] = (h1 ? sA[2 * i + 1] : sA[2 * i]) + dA;
                    uB[i] = (h1 ? sB[2 * i + 1] : sB[2 * i]) + dB;
                }
                {
                    float gA = h2 ? uA[0] : uA[1];
                    float gB = h2 ? uB[0] : uB[1];
                    float dA = __shfl_xor_sync(0xffffffffu, gA, 4);
                    float dB = __shfl_xor_sync(0xffffffffu, gB, 4);
                    float totA = (h2 ? uA[1] : uA[0]) + dA;
                    float totB = (h2 ? uB[1] : uB[0]) + dB;
                    float othA = __shfl_xor_sync(0xffffffffu, totA, 4);
                    float othB = __shfl_xor_sync(0xffffffffu, totB, 4);
                    if (c < 4) {
                        // reference denom = sqrt(qv)+1e-6; qv bounded away
                        // from 0, so av*rsqrt(qv) is within ~1e-5 rel of it.
                        float qA = fmaxf(othA, 1e-20f);
                        float qB = fmaxf(othB, 1e-20f);
                        orow[wlbA + c] = totA * rsqrtf(qA);
                        orow[wlbB + c] = totB * rsqrtf(qB);
                    }
                }
            }

            buf ^= 1;
            if (nxt >= NTASK) break;
            task = nxt;
        }
    }

    // ---- reset for next graph replay: last block out resets everything ----
    if (t == 0) {
        int old = atomicAdd(&gDone, 1);
        if (old == (int)gridDim.x - 1) {
            atomicExch(&gCtr, 0);
            atomicExch(&gFlag, 0);
            atomicExch(&gDone, 0);
        }
    }
}

// ---------------------------------------------------------------------------
extern "C" void kernel_launch(void* const* d_in, const int* in_sizes, int n_in,
                              void* d_out, int out_size) {
    const float* in_tensor = (const float*)d_in[0];
    const float* w_pred    = (const float*)d_in[1];
    const float* b_pred    = (const float*)d_in[2];
    float* out = (float*)d_out;

    coda_main_kernel<<<GRID, 128>>>(in_tensor, w_pred, b_pred, out);
}

// round 14
// speedup vs baseline: 1.2402x; 1.0445x over previous
#include <cuda_runtime.h>
#include <math.h>

// ---------------------------------------------------------------------------
// CoDAConv2d rewritten (single fused kernel):
//   act_o  = sum_c x_c * (A_o^T nb)_c + nb.b_o
//   norm_o = sqrt(x^T G_o x + 2 u_o^T x + s_o) + eps
// Thread t=(o,c). f32x2 packed FMA; 4px register blocking; paired groups with
// dual interleaved butterfly; double-buffered tile (one barrier/task);
// block-0 fused prep with spin; atomic task scheduler with prefetch.
// NEW: conv inner loop is explicitly software-pipelined over columns (next
// column's LDS issues before current column's FFMAs) so the 29cy LDS latency
// is covered by FFMA2 issue instead of (absent) occupancy. m-accumulators
// reduced 4->2 chains per px to fund the pipeline registers.
// ---------------------------------------------------------------------------

#define B_  4
#define CI  8
#define CO  16
#define HH  112
#define WW  112
#define PATCH 72

#define CHUNK 16
#define COLS  (CHUNK + 2)               // 18
#define TILE_ELEMS (3 * COLS * 8)       // 432
#define NCHUNK (WW / CHUNK)             // 7
#define NTASK  (B_ * HH * NCHUNK)       // 3136
#define GRID   444                      // 148 SMs * 3 blocks (all resident)

typedef unsigned long long ull;

// packed-pair tables (index t = o*8+c)
__device__ ull   gF2[36 * 128];
__device__ float gZ[9 * 128];
__device__ ull   gQ2[4 * 128];
__device__ float gU[128];
__device__ float gS[128];
__device__ int   gCtr  = 0;
__device__ int   gDone = 0;
__device__ int   gFlag = 0;

// --- f32x2 helpers -----------------------------------------------------------
__device__ __forceinline__ ull ffma2(ull a, ull b, ull c) {
    ull d; asm("fma.rn.f32x2 %0, %1, %2, %3;" : "=l"(d) : "l"(a), "l"(b), "l"(c));
    return d;
}
__device__ __forceinline__ ull fadd2(ull a, ull b) {
    ull d; asm("add.rn.f32x2 %0, %1, %2;" : "=l"(d) : "l"(a), "l"(b));
    return d;
}
__device__ __forceinline__ ull pack2(float lo, float hi) {
    ull d; asm("mov.b64 %0, {%1, %2};" : "=l"(d) : "f"(lo), "f"(hi));
    return d;
}
__device__ __forceinline__ float hsum2(ull a) {
    float lo, hi; asm("mov.b64 {%0, %1}, %2;" : "=f"(lo), "=f"(hi) : "l"(a));
    return lo + hi;
}

// --- prefetch loader --------------------------------------------------------
__device__ __forceinline__ void load_task(const float* __restrict__ in,
                                          int task, int t, float pre[4]) {
    const int rowid = task / NCHUNK;
    const int cw    = (task % NCHUNK) * CHUNK;
    const int b     = rowid / HH;
    const int h     = rowid % HH;
    #pragma unroll
    for (int k = 0; k < 4; k++) {
        int idx = t + k * 128;
        float v = 0.f;
        if (idx < TILE_ELEMS) {
            int ch   = idx & 7;
            int rest = idx >> 3;
            int col  = rest % COLS;
            int r    = rest / COLS;
            int ir   = h - 1 + r;
            int ic   = cw - 1 + col;
            if ((unsigned)ir < (unsigned)HH && (unsigned)ic < (unsigned)WW)
                v = __ldg(&in[((b * CI + ch) * HH + ir) * WW + ic]);
        }
        pre[k] = v;
    }
}

// --- one group's conv, software-pipelined over 18 column visits --------------
// r[0..3]=av partials, r[4..7]=qv partials
__device__ __forceinline__ void conv_group(const float tile[3][COLS][8],
                                           int wlb, int c,
                                           const ull* Fp, const float* Zreg,
                                           const ull* Qp, ull qinit, float Qs,
                                           float r[8]) {
    ull  m0[4], m1[4];
    float z[4], xc[4];
    ull  qp[4];
    #pragma unroll
    for (int px = 0; px < 4; px++) { m0[px] = 0ull; m1[px] = 0ull; z[px] = 0.f; }

    // preload column visit 0 (dh=0, k=0)
    const float* pv0 = &tile[0][wlb][0];
    ulonglong2 VA = *(const ulonglong2*)pv0;
    ulonglong2 VB = *((const ulonglong2*)pv0 + 1);
    float      vc = pv0[c];

    #pragma unroll
    for (int it = 0; it < 18; it++) {
        const int dh = it / 6;
        const int k  = it % 6;

        // issue next column's loads BEFORE using the current column
        ulonglong2 nVA, nVB;
        float      nvc;
        if (it < 17) {
            const int ndh = (it + 1) / 6;
            const int nk  = (it + 1) % 6;
            const float* pn = &tile[ndh][wlb + nk][0];
            nVA = *(const ulonglong2*)pn;
            nVB = *((const ulonglong2*)pn + 1);
            nvc = pn[c];
        }

        const int pxlo = (k - 2 > 0) ? (k - 2) : 0;
        const int pxhi = (k < 3) ? k : 3;
        #pragma unroll
        for (int px = pxlo; px <= pxhi; px++) {
            const int j = dh * 3 + (k - px);
            m0[px] = ffma2(VA.x, Fp[ 0 + j], m0[px]);
            m1[px] = ffma2(VA.y, Fp[ 9 + j], m1[px]);
            m0[px] = ffma2(VB.x, Fp[18 + j], m0[px]);
            m1[px] = ffma2(VB.y, Fp[27 + j], m1[px]);
            z[px]  = fmaf(vc, Zreg[j], z[px]);
        }
        if (dh == 1 && k >= 1 && k <= 4) {
            const int px = k - 1;
            xc[px] = vc;
            ull qa = ffma2(VA.x, Qp[0], qinit);
            qa = ffma2(VB.x, Qp[2], qa);
            ull qb = ffma2(VA.y, Qp[1], 0ull);
            qb = ffma2(VB.y, Qp[3], qb);
            qp[px] = fadd2(qa, qb);
        }

        if (it < 17) { VA = nVA; VB = nVB; vc = nvc; }
    }

    #pragma unroll
    for (int px = 0; px < 4; px++) {
        float m = hsum2(fadd2(m0[px], m1[px]));
        r[px]     = fmaf(xc[px], m, z[px]);
        r[px + 4] = fmaf(xc[px], hsum2(qp[px]), Qs);
    }
}

// --- main kernel ----------------------------------------------------------------
__global__ __launch_bounds__(128, 3)
void coda_main_kernel(const float* __restrict__ in,
                      const float* __restrict__ w_pred,
                      const float* __restrict__ b_pred,
                      float* __restrict__ out) {
    const int t = threadIdx.x;
    const int o = t >> 3;
    const int c = t & 7;

    // ===== fused prep: block 0 builds tables; everyone else waits ==========
    if (blockIdx.x == 0) {
        #pragma unroll 4
        for (int bx = 0; bx < 36; bx++) {
            const int i = bx / 9, j = bx % 9;
            float lo = w_pred[(((2 * i)     * 9 + j) * 16 + o) * 8 + c];
            float hi = w_pred[(((2 * i + 1) * 9 + j) * 16 + o) * 8 + c];
            gF2[bx * 128 + t] = pack2(lo, hi);
            if (bx < 9) gZ[bx * 128 + t] = b_pred[(c * 9 + bx) * 16 + o];
        }
        float G8[8] = {0.f, 0.f, 0.f, 0.f, 0.f, 0.f, 0.f, 0.f};
        float uacc = 0.f, ssum = 0.f;
        #pragma unroll 4
        for (int p = 0; p < PATCH; p++) {
            const float wc = w_pred[(p * 16 + o) * 8 + c];
            const float4 k0 = *(const float4*)&w_pred[(p * 16 + o) * 8];
            const float4 k1 = *(const float4*)&w_pred[(p * 16 + o) * 8 + 4];
            const float bv = b_pred[p * 16 + o];
            G8[0] = fmaf(wc, k0.x, G8[0]); G8[1] = fmaf(wc, k0.y, G8[1]);
            G8[2] = fmaf(wc, k0.z, G8[2]); G8[3] = fmaf(wc, k0.w, G8[3]);
            G8[4] = fmaf(wc, k1.x, G8[4]); G8[5] = fmaf(wc, k1.y, G8[5]);
            G8[6] = fmaf(wc, k1.z, G8[6]); G8[7] = fmaf(wc, k1.w, G8[7]);
            uacc = fmaf(wc, bv, uacc);
            ssum = fmaf(bv, bv, ssum);
        }
        #pragma unroll
        for (int kk = 0; kk < 4; kk++)
            gQ2[kk * 128 + t] = pack2(G8[2 * kk], G8[2 * kk + 1]);
        gU[t] = 2.0f * uacc;
        gS[t] = ssum * 0.125f;

        __threadfence();
        __syncthreads();
        if (t == 0) atomicExch(&gFlag, 1);   // release
    } else {
        if (t == 0) {
            while (atomicAdd(&gFlag, 0) == 0) __nanosleep(64);
        }
        __syncthreads();
        __threadfence();                      // acquire
    }

    // ===== per-thread constant tables =======================================
    ull Fp[36];
    #pragma unroll
    for (int p = 0; p < 36; p++) Fp[p] = gF2[p * 128 + t];
    float Zreg[9];
    #pragma unroll
    for (int j = 0; j < 9; j++) Zreg[j] = gZ[j * 128 + t];
    ull Qp[4];
    #pragma unroll
    for (int k = 0; k < 4; k++) Qp[k] = gQ2[k * 128 + t];
    const ull   qinit = pack2(gU[t], 0.f);
    const float Qs    = gS[t];

    __shared__ float tile[2][3][COLS][8];   // double buffer
    __shared__ int   sTask;

    float pre[4];
    int buf = 0;

    if (t == 0) sTask = atomicAdd(&gCtr, 1);
    __syncthreads();
    int task = sTask;
    if (task < NTASK) {
        load_task(in, task, t, pre);

        while (true) {
            // publish prefetched tile into current buffer
            #pragma unroll
            for (int k = 0; k < 4; k++) {
                int idx = t + k * 128;
                if (idx < TILE_ELEMS) ((float*)tile[buf])[idx] = pre[k];
            }
            if (t == 0) sTask = atomicAdd(&gCtr, 1);
            __syncthreads();                   // single barrier per task
            const int nxt = sTask;
            if (nxt < NTASK) load_task(in, nxt, t, pre);

            const int rowid = task / NCHUNK;
            const int cw    = (task % NCHUNK) * CHUNK;
            const int b     = rowid / HH;
            const int h     = rowid % HH;
            float* orow = &out[((b * CO + o) * HH + h) * WW + cw];

            // paired groups: conv A, conv B, dual interleaved reduction
            #pragma unroll 1
            for (int half = 0; half < 2; half++) {
                const int wlbA = half * 8;
                const int wlbB = wlbA + 4;

                float rA[8], rB[8];
                conv_group(tile[buf], wlbA, c, Fp, Zreg, Qp, qinit, Qs, rA);
                conv_group(tile[buf], wlbB, c, Fp, Zreg, Qp, qinit, Qs, rB);

                // dual interleaved 8-value / 8-lane butterfly reductions
                const bool h0 = c & 1, h1 = c & 2, h2 = c & 4;
                float sA[4], sB[4];
                #pragma unroll
                for (int i = 0; i < 4; i++) {
                    float gA = h0 ? rA[2 * i] : rA[2 * i + 1];
                    float gB = h0 ? rB[2 * i] : rB[2 * i + 1];
                    float dA = __shfl_xor_sync(0xffffffffu, gA, 1);
                    float dB = __shfl_xor_sync(0xffffffffu, gB, 1);
                    sA[i] = (h0 ? rA[2 * i + 1] : rA[2 * i]) + dA;
                    sB[i] = (h0 ? rB[2 * i + 1] : rB[2 * i]) + dB;
                }
                float uA[2], uB[2];
                #pragma unroll
                for (int i = 0; i < 2; i++) {
                    float gA = h1 ? sA[2 * i] : sA[2 * i + 1];
                    float gB = h1 ? sB[2 * i] : sB[2 * i + 1];
                    float dA = __shfl_xor_sync(0xffffffffu, gA, 2);
                    float dB = __shfl_xor_sync(0xffffffffu, gB, 2);
                    uA[i] = (h1 ? sA[2 * i + 1] : sA[2 * i]) + dA;
                    uB[i] = (h1 ? sB[2 * i + 1] : sB[2 * i]) + dB;
                }
                {
                    float gA = h2 ? uA[0] : uA[1];
                    float gB = h2 ? uB[0] : uB[1];
                    float dA = __shfl_xor_sync(0xffffffffu, gA, 4);
                    float dB = __shfl_xor_sync(0xffffffffu, gB, 4);
                    float totA = (h2 ? uA[1] : uA[0]) + dA;
                    float totB = (h2 ? uB[1] : uB[0]) + dB;
                    float othA = __shfl_xor_sync(0xffffffffu, totA, 4);
                    float othB = __shfl_xor_sync(0xffffffffu, totB, 4);
                    if (c < 4) {
                        // reference denom = sqrt(qv)+1e-6; qv bounded away
                        // from 0, so av*rsqrt(qv) is within ~1e-5 rel of it.
                        float qA = fmaxf(othA, 1e-20f);
                        float qB = fmaxf(othB, 1e-20f);
                        orow[wlbA + c] = totA * rsqrtf(qA);
                        orow[wlbB + c] = totB * rsqrtf(qB);
                    }
                }
            }

            buf ^= 1;
            if (nxt >= NTASK) break;
            task = nxt;
        }
    }

    // ---- reset for next graph replay: last block out resets everything ----
    if (t == 0) {
        int old = atomicAdd(&gDone, 1);
        if (old == (int)gridDim.x - 1) {
            atomicExch(&gCtr, 0);
            atomicExch(&gFlag, 0);
            atomicExch(&gDone, 0);
        }
    }
}

// ---------------------------------------------------------------------------
extern "C" void kernel_launch(void* const* d_in, const int* in_sizes, int n_in,
                              void* d_out, int out_size) {
    const float* in_tensor = (const float*)d_in[0];
    const float* w_pred    = (const float*)d_in[1];
    const float* b_pred    = (const float*)d_in[2];
    float* out = (float*)d_out;

    coda_main_kernel<<<GRID, 128>>>(in_tensor, w_pred, b_pred, out);
}

// round 15
// speedup vs baseline: 1.2775x; 1.0300x over previous
#include <cuda_runtime.h>
#include <math.h>

// ---------------------------------------------------------------------------
// CoDAConv2d rewritten (single fused kernel):
//   act_o  = sum_c x_c * (A_o^T nb)_c + nb.b_o
//   norm_o = sqrt(x^T G_o x + 2 u_o^T x + s_o) + eps
// Thread t=(o,c). f32x2 packed FMA. NEW: each 8-px half is ONE fused 10-col x
// 3-row sweep feeding all 8 pixels (no duplicated column loads), with
// distance-1 software pipelining of the column LDS. Single m-chain per px;
// qv folded to scalar at its center visit. 16-value/8-lane butterfly per
// half; all 8 lanes store. Double-buffered tile (one barrier/task); block-0
// fused prep with spin; atomic task scheduler with prefetch; rsqrt epilogue.
// ---------------------------------------------------------------------------

#define B_  4
#define CI  8
#define CO  16
#define HH  112
#define WW  112
#define PATCH 72

#define CHUNK 16
#define COLS  (CHUNK + 2)               // 18
#define TILE_ELEMS (3 * COLS * 8)       // 432
#define NCHUNK (WW / CHUNK)             // 7
#define NTASK  (B_ * HH * NCHUNK)       // 3136
#define GRID   444                      // 148 SMs * 3 blocks (all resident)

typedef unsigned long long ull;

// packed-pair tables (index t = o*8+c)
__device__ ull   gF2[36 * 128];
__device__ float gZ[9 * 128];
__device__ ull   gQ2[4 * 128];
__device__ float gU[128];
__device__ float gS[128];
__device__ int   gCtr  = 0;
__device__ int   gDone = 0;
__device__ int   gFlag = 0;

// --- f32x2 helpers -----------------------------------------------------------
__device__ __forceinline__ ull ffma2(ull a, ull b, ull c) {
    ull d; asm("fma.rn.f32x2 %0, %1, %2, %3;" : "=l"(d) : "l"(a), "l"(b), "l"(c));
    return d;
}
__device__ __forceinline__ ull fadd2(ull a, ull b) {
    ull d; asm("add.rn.f32x2 %0, %1, %2;" : "=l"(d) : "l"(a), "l"(b));
    return d;
}
__device__ __forceinline__ ull pack2(float lo, float hi) {
    ull d; asm("mov.b64 %0, {%1, %2};" : "=l"(d) : "f"(lo), "f"(hi));
    return d;
}
__device__ __forceinline__ float hsum2(ull a) {
    float lo, hi; asm("mov.b64 {%0, %1}, %2;" : "=f"(lo), "=f"(hi) : "l"(a));
    return lo + hi;
}

// --- prefetch loader --------------------------------------------------------
__device__ __forceinline__ void load_task(const float* __restrict__ in,
                                          int task, int t, float pre[4]) {
    const int rowid = task / NCHUNK;
    const int cw    = (task % NCHUNK) * CHUNK;
    const int b     = rowid / HH;
    const int h     = rowid % HH;
    #pragma unroll
    for (int k = 0; k < 4; k++) {
        int idx = t + k * 128;
        float v = 0.f;
        if (idx < TILE_ELEMS) {
            int ch   = idx & 7;
            int rest = idx >> 3;
            int col  = rest % COLS;
            int r    = rest / COLS;
            int ir   = h - 1 + r;
            int ic   = cw - 1 + col;
            if ((unsigned)ir < (unsigned)HH && (unsigned)ic < (unsigned)WW)
                v = __ldg(&in[((b * CI + ch) * HH + ir) * WW + ic]);
        }
        pre[k] = v;
    }
}

// --- fused 8-pixel half-sweep: 10 cols x 3 rows, software-pipelined ----------
// rv[px]=av partial, rq[px]=qv partial (to be lane-reduced)
__device__ __forceinline__ void conv_half(const float tile[3][COLS][8],
                                          int wlb, int c,
                                          const ull* Fp, const float* Zreg,
                                          const ull* Qp, ull qinit, float Qs,
                                          float rv[8], float rq[8]) {
    ull   m[8];
    float z[8], xc[8];
    #pragma unroll
    for (int px = 0; px < 8; px++) { m[px] = 0ull; z[px] = 0.f; }

    // preload visit 0 (dh=0, k=0)
    const float* pv0 = &tile[0][wlb][0];
    ulonglong2 VA = *(const ulonglong2*)pv0;
    ulonglong2 VB = *((const ulonglong2*)pv0 + 1);
    float      vc = pv0[c];

    #pragma unroll
    for (int it = 0; it < 30; it++) {
        const int dh = it / 10;
        const int k  = it % 10;

        // issue next column's loads BEFORE using the current column
        ulonglong2 nVA, nVB;
        float      nvc;
        if (it < 29) {
            const int ndh = (it + 1) / 10;
            const int nk  = (it + 1) % 10;
            const float* pn = &tile[ndh][wlb + nk][0];
            nVA = *(const ulonglong2*)pn;
            nVB = *((const ulonglong2*)pn + 1);
            nvc = pn[c];
        }

        const int pxlo = (k - 2 > 0) ? (k - 2) : 0;
        const int pxhi = (k < 7) ? k : 7;
        #pragma unroll
        for (int px = pxlo; px <= pxhi; px++) {
            const int j = dh * 3 + (k - px);
            m[px] = ffma2(VA.x, Fp[ 0 + j], m[px]);
            m[px] = ffma2(VA.y, Fp[ 9 + j], m[px]);
            m[px] = ffma2(VB.x, Fp[18 + j], m[px]);
            m[px] = ffma2(VB.y, Fp[27 + j], m[px]);
            z[px] = fmaf(vc, Zreg[j], z[px]);
        }
        if (dh == 1 && k >= 1 && k <= 8) {
            const int px = k - 1;
            xc[px] = vc;
            ull qa = ffma2(VA.x, Qp[0], qinit);
            qa = ffma2(VB.x, Qp[2], qa);
            ull qb = ffma2(VA.y, Qp[1], 0ull);
            qb = ffma2(VB.y, Qp[3], qb);
            rq[px] = fmaf(vc, hsum2(fadd2(qa, qb)), Qs);
        }

        if (it < 29) { VA = nVA; VB = nVB; vc = nvc; }
    }

    #pragma unroll
    for (int px = 0; px < 8; px++)
        rv[px] = fmaf(xc[px], hsum2(m[px]), z[px]);
}

// --- main kernel ----------------------------------------------------------------
__global__ __launch_bounds__(128, 3)
void coda_main_kernel(const float* __restrict__ in,
                      const float* __restrict__ w_pred,
                      const float* __restrict__ b_pred,
                      float* __restrict__ out) {
    const int t = threadIdx.x;
    const int o = t >> 3;
    const int c = t & 7;

    // ===== fused prep: block 0 builds tables; everyone else waits ==========
    if (blockIdx.x == 0) {
        #pragma unroll 4
        for (int bx = 0; bx < 36; bx++) {
            const int i = bx / 9, j = bx % 9;
            float lo = w_pred[(((2 * i)     * 9 + j) * 16 + o) * 8 + c];
            float hi = w_pred[(((2 * i + 1) * 9 + j) * 16 + o) * 8 + c];
            gF2[bx * 128 + t] = pack2(lo, hi);
            if (bx < 9) gZ[bx * 128 + t] = b_pred[(c * 9 + bx) * 16 + o];
        }
        float G8[8] = {0.f, 0.f, 0.f, 0.f, 0.f, 0.f, 0.f, 0.f};
        float uacc = 0.f, ssum = 0.f;
        #pragma unroll 4
        for (int p = 0; p < PATCH; p++) {
            const float wc = w_pred[(p * 16 + o) * 8 + c];
            const float4 k0 = *(const float4*)&w_pred[(p * 16 + o) * 8];
            const float4 k1 = *(const float4*)&w_pred[(p * 16 + o) * 8 + 4];
            const float bv = b_pred[p * 16 + o];
            G8[0] = fmaf(wc, k0.x, G8[0]); G8[1] = fmaf(wc, k0.y, G8[1]);
            G8[2] = fmaf(wc, k0.z, G8[2]); G8[3] = fmaf(wc, k0.w, G8[3]);
            G8[4] = fmaf(wc, k1.x, G8[4]); G8[5] = fmaf(wc, k1.y, G8[5]);
            G8[6] = fmaf(wc, k1.z, G8[6]); G8[7] = fmaf(wc, k1.w, G8[7]);
            uacc = fmaf(wc, bv, uacc);
            ssum = fmaf(bv, bv, ssum);
        }
        #pragma unroll
        for (int kk = 0; kk < 4; kk++)
            gQ2[kk * 128 + t] = pack2(G8[2 * kk], G8[2 * kk + 1]);
        gU[t] = 2.0f * uacc;
        gS[t] = ssum * 0.125f;

        __threadfence();
        __syncthreads();
        if (t == 0) atomicExch(&gFlag, 1);   // release
    } else {
        if (t == 0) {
            while (atomicAdd(&gFlag, 0) == 0) __nanosleep(64);
        }
        __syncthreads();
        __threadfence();                      // acquire
    }

    // ===== per-thread constant tables =======================================
    ull Fp[36];
    #pragma unroll
    for (int p = 0; p < 36; p++) Fp[p] = gF2[p * 128 + t];
    float Zreg[9];
    #pragma unroll
    for (int j = 0; j < 9; j++) Zreg[j] = gZ[j * 128 + t];
    ull Qp[4];
    #pragma unroll
    for (int k = 0; k < 4; k++) Qp[k] = gQ2[k * 128 + t];
    const ull   qinit = pack2(gU[t], 0.f);
    const float Qs    = gS[t];

    __shared__ float tile[2][3][COLS][8];   // double buffer
    __shared__ int   sTask;

    float pre[4];
    int buf = 0;

    if (t == 0) sTask = atomicAdd(&gCtr, 1);
    __syncthreads();
    int task = sTask;
    if (task < NTASK) {
        load_task(in, task, t, pre);

        while (true) {
            // publish prefetched tile into current buffer
            #pragma unroll
            for (int k = 0; k < 4; k++) {
                int idx = t + k * 128;
                if (idx < TILE_ELEMS) ((float*)tile[buf])[idx] = pre[k];
            }
            if (t == 0) sTask = atomicAdd(&gCtr, 1);
            __syncthreads();                   // single barrier per task
            const int nxt = sTask;
            if (nxt < NTASK) load_task(in, nxt, t, pre);

            const int rowid = task / NCHUNK;
            const int cw    = (task % NCHUNK) * CHUNK;
            const int b     = rowid / HH;
            const int h     = rowid % HH;
            float* orow = &out[((b * CO + o) * HH + h) * WW + cw];

            #pragma unroll
            for (int half = 0; half < 2; half++) {
                const int wlb = half * 8;

                float rv[8], rq[8];
                conv_half(tile[buf], wlb, c, Fp, Zreg, Qp, qinit, Qs, rv, rq);

                // 16-value / 8-lane butterfly: lane c ends with (av, qv) of px=c
                const bool h0 = c & 1, h1 = c & 2, h2 = c & 4;
                float sv[4], sq[4];
                #pragma unroll
                for (int i = 0; i < 4; i++) {
                    float gv = h0 ? rv[2 * i] : rv[2 * i + 1];
                    float gq = h0 ? rq[2 * i] : rq[2 * i + 1];
                    float dv = __shfl_xor_sync(0xffffffffu, gv, 1);
                    float dq = __shfl_xor_sync(0xffffffffu, gq, 1);
                    sv[i] = (h0 ? rv[2 * i + 1] : rv[2 * i]) + dv;
                    sq[i] = (h0 ? rq[2 * i + 1] : rq[2 * i]) + dq;
                }
                float uv[2], uq[2];
                #pragma unroll
                for (int i = 0; i < 2; i++) {
                    float gv = h1 ? sv[2 * i] : sv[2 * i + 1];
                    float gq = h1 ? sq[2 * i] : sq[2 * i + 1];
                    float dv = __shfl_xor_sync(0xffffffffu, gv, 2);
                    float dq = __shfl_xor_sync(0xffffffffu, gq, 2);
                    uv[i] = (h1 ? sv[2 * i + 1] : sv[2 * i]) + dv;
                    uq[i] = (h1 ? sq[2 * i + 1] : sq[2 * i]) + dq;
                }
                {
                    float gv = h2 ? uv[0] : uv[1];
                    float gq = h2 ? uq[0] : uq[1];
                    float dv = __shfl_xor_sync(0xffffffffu, gv, 4);
                    float dq = __shfl_xor_sync(0xffffffffu, gq, 4);
                    float av = (h2 ? uv[1] : uv[0]) + dv;   // full sum, px = c
                    float qv = (h2 ? uq[1] : uq[0]) + dq;
                    // reference denom = sqrt(qv)+1e-6; qv bounded away from 0,
                    // so av * rsqrt(qv) is within ~1e-5 relative of it.
                    qv = fmaxf(qv, 1e-20f);
                    orow[wlb + c] = av * rsqrtf(qv);        // all 8 lanes store
                }
            }

            buf ^= 1;
            if (nxt >= NTASK) break;
            task = nxt;
        }
    }

    // ---- reset for next graph replay: last block out resets everything ----
    if (t == 0) {
        int old = atomicAdd(&gDone, 1);
        if (old == (int)gridDim.x - 1) {
            atomicExch(&gCtr, 0);
            atomicExch(&gFlag, 0);
            atomicExch(&gDone, 0);
        }
    }
}

// ---------------------------------------------------------------------------
extern "C" void kernel_launch(void* const* d_in, const int* in_sizes, int n_in,
                              void* d_out, int out_size) {
    const float* in_tensor = (const float*)d_in[0];
    const float* w_pred    = (const float*)d_in[1];
    const float* b_pred    = (const float*)d_in[2];
    float* out = (float*)d_out;

    coda_main_kernel<<<GRID, 128>>>(in_tensor, w_pred, b_pred, out);
}